// round 5
// baseline (speedup 1.0000x reference)
#include <cuda_runtime.h>
#include <cstdint>

// SpectralWindowPreprocessor: out[b,c,j,h,w] = x[b, reflect(c+j-3), h, w]
// B=4, C=31, J=7 (window 3, reflect), H=W=512. Mask is all-ones under
// 'reflect' mode, so this is a pure plane-gather copy.
//
// Shapes:
//   x   : (4, 31, 512, 512) fp32          = 130 MB
//   out : (4, 31, 7, 512, 512) fp32       = 910 MB
//
// Pure bandwidth problem. One float4 per thread, plane-indexed grid.

static constexpr int C       = 31;
static constexpr int J       = 7;          // 2*3 + 1
static constexpr int HW_VEC  = 65536;      // 512*512 / 4 float4s per plane
static constexpr int PLANES  = 4 * C * J;  // 868 output planes
static constexpr int TPB     = 256;

__global__ __launch_bounds__(TPB)
void spectral_window_kernel(const float4* __restrict__ x,
                            float4* __restrict__ out) {
    // Output plane id: plane = ((b*C + c)*J + j)
    const int plane = blockIdx.y;
    const int p     = blockIdx.x * TPB + threadIdx.x;   // 0 .. HW_VEC-1

    const int j  = plane % J;
    const int bc = plane / J;        // b*C + c
    const int c  = bc % C;
    const int b  = bc / C;

    // reflect padding: t in [c-3, c+3] mapped into [0, C)
    int t = c + j - 3;
    if (t < 0)       t = -t - 1;
    else if (t >= C) t = 2 * C - t - 1;

    const size_t src = (size_t)(b * C + t) * HW_VEC + p;
    const size_t dst = (size_t)plane       * HW_VEC + p;
    out[dst] = x[src];
}

extern "C" void kernel_launch(void* const* d_in, const int* in_sizes, int n_in,
                              void* d_out, int out_size) {
    const float4* x   = (const float4*)d_in[0];
    float4*       out = (float4*)d_out;

    dim3 grid(HW_VEC / TPB, PLANES, 1);   // (256, 868)
    spectral_window_kernel<<<grid, TPB>>>(x, out);
}

// round 7
// speedup vs baseline: 1.0102x; 1.0102x over previous
#include <cuda_runtime.h>
#include <cstdint>

// SpectralWindowPreprocessor: out[b,c,j,h,w] = x[b, reflect(c+j-3), h, w]
// B=4, C=31, J=7 (window 3, reflect), H=W=512. Reflect mode -> mask all-ones
// -> pure plane-gather copy. 910 MB write + 130 MB read; HBM-bound.
//
// R5 changes vs R3 (155.7us, DRAM 76%, alu 60%):
//  - 4x float4 per thread: amortize plane-index ALU, MLP=4 front-batched LDGs
//  - __stcs streaming stores: don't let the 910MB write stream evict the
//    ~7MB read working set from L2 (reads have 7x reuse)

static constexpr int C       = 31;
static constexpr int J       = 7;           // 2*3 + 1
static constexpr int HW_VEC  = 65536;       // 512*512/4 float4s per plane
static constexpr int PLANES  = 4 * C * J;   // 868 output planes
static constexpr int TPB     = 256;
static constexpr int VPT     = 4;           // float4s per thread (64 B)

__global__ __launch_bounds__(TPB)
void spectral_window_kernel(const float4* __restrict__ x,
                            float4* __restrict__ out) {
    const int plane = blockIdx.y;                 // ((b*C + c)*J + j)
    const int base  = (blockIdx.x * TPB) * VPT + threadIdx.x;

    const int j  = plane % J;
    const int bc = plane / J;                     // b*C + c
    const int c  = bc % C;
    const int b  = bc / C;

    // reflect padding: t = c + j - 3 mapped into [0, C)
    int t = c + j - 3;
    if (t < 0)       t = -t - 1;
    else if (t >= C) t = 2 * C - t - 1;

    const float4* src = x   + (size_t)(b * C + t) * HW_VEC + base;
    float4*       dst = out + (size_t)plane       * HW_VEC + base;

    // 4 independent 128-bit loads batched up front (MLP=4), then 4
    // evict-first streaming stores. Stride TPB keeps each access coalesced.
    float4 v0 = __ldg(src + 0 * TPB);
    float4 v1 = __ldg(src + 1 * TPB);
    float4 v2 = __ldg(src + 2 * TPB);
    float4 v3 = __ldg(src + 3 * TPB);
    __stcs(dst + 0 * TPB, v0);
    __stcs(dst + 1 * TPB, v1);
    __stcs(dst + 2 * TPB, v2);
    __stcs(dst + 3 * TPB, v3);
}

extern "C" void kernel_launch(void* const* d_in, const int* in_sizes, int n_in,
                              void* d_out, int out_size) {
    const float4* x   = (const float4*)d_in[0];
    float4*       out = (float4*)d_out;

    dim3 grid(HW_VEC / (TPB * VPT), PLANES, 1);   // (64, 868)
    spectral_window_kernel<<<grid, TPB>>>(x, out);
}